// round 8
// baseline (speedup 1.0000x reference)
#include <cuda_runtime.h>
#include <math.h>
#include <stdint.h>

// Problem constants
constexpr int T_SEQ  = 2048;
constexpr int NB     = 2;
constexpr int NH     = 4;
constexpr int DK     = 256;
constexpr int DV     = 512;
constexpr int DMODEL = 1024;
constexpr int KDIM   = NH * DK;    // 1024
constexpr int VDIM   = NH * DV;    // 2048
constexpr int MROWS  = NB * T_SEQ; // 4096
constexpr int CHK    = 128;
constexpr int NCH    = T_SEQ / CHK; // 16
constexpr int STSZ   = DV * DK;     // 131072

// Scratch (device globals; no allocations allowed)
__device__ __align__(128) float g_q[MROWS * KDIM];
__device__ __align__(128) float g_k[MROWS * KDIM];
__device__ __align__(128) float g_v[MROWS * VDIM];
__device__ __align__(128) float g_g[MROWS * VDIM];
__device__ __align__(128) float g_o[MROWS * VDIM];
__device__ __align__(128) float g_x[MROWS * DMODEL];         // rounded x
__device__ __align__(128) float g_w[8 * 1024 * 1024];        // rounded weights
__device__ __align__(128) float g_state[NB * NH * NCH * STSZ];

// weight offsets in g_w (floats)
constexpr long long WQ_OFF = 0;
constexpr long long WK_OFF = 1048576;
constexpr long long WV_OFF = 2097152;
constexpr long long WG_OFF = 4194304;
constexpr long long WO_OFF = 6291456;

__device__ __forceinline__ unsigned f2tf(float f) {
    unsigned u;
    asm("cvt.rna.tf32.f32 %0, %1;" : "=r"(u) : "f"(f));
    return u;
}
__device__ __forceinline__ float roundtf(float f) { return __uint_as_float(f2tf(f)); }

__device__ __forceinline__ void mma_tf32(float* c, const unsigned* a, const unsigned* b) {
    asm volatile(
        "mma.sync.aligned.m16n8k8.row.col.f32.tf32.tf32.f32 "
        "{%0,%1,%2,%3}, {%4,%5,%6,%7}, {%8,%9}, {%0,%1,%2,%3};\n"
        : "+f"(c[0]), "+f"(c[1]), "+f"(c[2]), "+f"(c[3])
        : "r"(a[0]), "r"(a[1]), "r"(a[2]), "r"(a[3]), "r"(b[0]), "r"(b[1]));
}

__device__ __forceinline__ float head_lam(int h) {
    return logf(1.0f - exp2f(-5.0f - (float)h));
}

__device__ __forceinline__ void cpasync16(unsigned dst, const void* src) {
    asm volatile("cp.async.cg.shared.global [%0], [%1], 16;\n" :: "r"(dst), "l"(src));
}
__device__ __forceinline__ void cp_commit() {
    asm volatile("cp.async.commit_group;\n" ::: "memory");
}
__device__ __forceinline__ void cp_wait1() {
    asm volatile("cp.async.wait_group 1;\n" ::: "memory");
}

// ---------------------------------------------------------------------------
// Rounding copy: src (external fp32) -> tf32-rounded scratch (g_x or g_w+off)
// ---------------------------------------------------------------------------
__global__ __launch_bounds__(256) void round_copy(
    const float* __restrict__ src, int dsel, long long doff, int n4)
{
    float* dst = ((dsel == 5) ? g_x : g_w) + doff;
    int i = blockIdx.x * 256 + threadIdx.x;
    if (i < n4) {
        float4 v = ((const float4*)src)[i];
        ((float4*)dst)[i] = make_float4(roundtf(v.x), roundtf(v.y),
                                        roundtf(v.z), roundtf(v.w));
    }
}

// ---------------------------------------------------------------------------
// Pipelined TF32 GEMM: C[128,256] tile, BK=32, 3-stage cp.async.
// 8 warps in 2(m) x 4(n) grid, warp tile 64x64 (halves LDS per FLOP vs 32x64).
// Inputs must already be tf32-rounded.
// ---------------------------------------------------------------------------
constexpr int A_W   = 128 * 36;             // words per A stage (pitch 36)
constexpr int B_W   = 256 * 36;             // words per B stage
constexpr int STG_W = A_W + B_W;            // 13824 words = 55296 B
constexpr int GEMM_SMEM = 3 * STG_W * 4;    // 165888 bytes

__device__ __forceinline__ void gemm_pipe(
    const float* __restrict__ Ab, const float* __restrict__ Wb,
    float* __restrict__ Cb, int ldc, int K, int roundC, unsigned* smem)
{
    const int tid  = threadIdx.x;
    const int lane = tid & 31;
    const int wid  = tid >> 5;
    const int wm = (wid & 1) * 64;    // 2 m-warps
    const int wn = (wid >> 1) * 64;   // 4 n-warps
    const int gq = lane >> 2;
    const int tq = lane & 3;
    const int nk = K >> 5;

    float acc[4][8][4];
#pragma unroll
    for (int mt = 0; mt < 4; mt++)
#pragma unroll
        for (int nt = 0; nt < 8; nt++)
#pragma unroll
            for (int e = 0; e < 4; e++) acc[mt][nt][e] = 0.0f;

    auto cp_chunk = [&](int c) {
        unsigned* As = smem + (c % 3) * STG_W;
        unsigned* Bs = As + A_W;
        const float* Ap = Ab + c * 32;
        const float* Bp = Wb + c * 32;
#pragma unroll
        for (int i = 0; i < 4; i++) {               // A: 128 rows x 8 float4
            int id = i * 256 + tid;
            int row = id >> 3, g = id & 7;
            cpasync16((unsigned)__cvta_generic_to_shared(&As[row * 36 + g * 4]),
                      Ap + (size_t)row * K + g * 4);
        }
#pragma unroll
        for (int i = 0; i < 8; i++) {               // B: 256 rows x 8 float4
            int id = i * 256 + tid;
            int row = id >> 3, g = id & 7;
            cpasync16((unsigned)__cvta_generic_to_shared(&Bs[row * 36 + g * 4]),
                      Bp + (size_t)row * K + g * 4);
        }
        cp_commit();
    };

    cp_chunk(0); cp_chunk(1);

    for (int j = 0; j < nk; j++) {
        cp_wait1();
        __syncthreads();
        if (j + 2 < nk) cp_chunk(j + 2);
        else cp_commit();

        unsigned* As = smem + (j % 3) * STG_W;
        unsigned* Bs = As + A_W;
#pragma unroll
        for (int kk = 0; kk < 32; kk += 8) {
            unsigned af[4][4];
#pragma unroll
            for (int mt = 0; mt < 4; mt++) {
                int r = wm + mt * 16 + gq;
                af[mt][0] = As[r * 36 + kk + tq];
                af[mt][1] = As[(r + 8) * 36 + kk + tq];
                af[mt][2] = As[r * 36 + kk + 4 + tq];
                af[mt][3] = As[(r + 8) * 36 + kk + 4 + tq];
            }
#pragma unroll
            for (int nt = 0; nt < 8; nt++) {
                int c = wn + nt * 8 + gq;
                unsigned bf[2];
                bf[0] = Bs[c * 36 + kk + tq];
                bf[1] = Bs[c * 36 + kk + 4 + tq];
#pragma unroll
                for (int mt = 0; mt < 4; mt++)
                    mma_tf32(acc[mt][nt], af[mt], bf);
            }
        }
        __syncthreads();
    }

#pragma unroll
    for (int mt = 0; mt < 4; mt++) {
        int r0 = wm + mt * 16 + gq;
#pragma unroll
        for (int nt = 0; nt < 8; nt++) {
            int cc = wn + nt * 8 + tq * 2;
            float2 v0 = make_float2(acc[mt][nt][0], acc[mt][nt][1]);
            float2 v1 = make_float2(acc[mt][nt][2], acc[mt][nt][3]);
            if (roundC) {
                v0.x = roundtf(v0.x); v0.y = roundtf(v0.y);
                v1.x = roundtf(v1.x); v1.y = roundtf(v1.y);
            }
            *(float2*)(Cb + (size_t)r0 * ldc + cc)       = v0;
            *(float2*)(Cb + (size_t)(r0 + 8) * ldc + cc) = v1;
        }
    }
}

// Fused projections: x @ {Wq,Wk,Wv,Wg}^T. grid (24, 32), 256-wide N tiles.
__global__ __launch_bounds__(256) void proj_gemm()
{
    extern __shared__ unsigned smem[];
    const int bnx = blockIdx.x;
    const int bm  = blockIdx.y * 128;

    const float* Wb; float* Cc; int ldc, col, roundC = 0;
    if (bnx < 4)       { Wb = g_w + WQ_OFF; Cc = g_q; ldc = 1024; col = bnx * 256; }
    else if (bnx < 8)  { Wb = g_w + WK_OFF; Cc = g_k; ldc = 1024; col = (bnx - 4) * 256; }
    else if (bnx < 16) { Wb = g_w + WV_OFF; Cc = g_v; ldc = 2048; col = (bnx - 8) * 256; roundC = 1; }
    else               { Wb = g_w + WG_OFF; Cc = g_g; ldc = 2048; col = (bnx - 16) * 256; }

    gemm_pipe(g_x + (size_t)bm * DMODEL, Wb + (size_t)col * DMODEL,
              Cc + (size_t)bm * ldc + col, ldc, DMODEL, roundC, smem);
}

// Output projection: (g_o rounded) @ Wo^T -> out. grid (4, 32).
__global__ __launch_bounds__(256) void out_gemm(float* __restrict__ out)
{
    extern __shared__ unsigned smem[];
    const int bn = blockIdx.x * 256;
    const int bm = blockIdx.y * 128;
    gemm_pipe(g_o + (size_t)bm * VDIM, g_w + WO_OFF + (size_t)bn * VDIM,
              out + (size_t)bm * DMODEL + bn, DMODEL, VDIM, 0, smem);
}

// ---------------------------------------------------------------------------
// RoPE (in place on g_q, g_k) + q scale by dk^-0.5 (fp32 path as reference).
// ---------------------------------------------------------------------------
__global__ __launch_bounds__(256) void rope_kernel()
{
    int idx = blockIdx.x * 256 + threadIdx.x;
    int i  = idx & 127;
    int h  = (idx >> 7) & 3;
    int bt = idx >> 9;
    int t  = bt & (T_SEQ - 1);
    size_t base = (size_t)bt * KDIM + h * DK;

    float e    = (float)(2 * i) * (1.0f / 256.0f);
    float invf = 1.0f / powf(10000.0f, e);
    float ang  = (float)t * invf;
    float sn, cs;
    sincosf(ang, &sn, &cs);

    float q1 = g_q[base + i], q2 = g_q[base + 128 + i];
    g_q[base + i]       = (q1 * cs - q2 * sn) * 0.0625f;
    g_q[base + 128 + i] = (q1 * sn + q2 * cs) * 0.0625f;
    float k1 = g_k[base + i], k2 = g_k[base + 128 + i];
    g_k[base + i]       = k1 * cs - k2 * sn;
    g_k[base + 128 + i] = k1 * sn + k2 * cs;
}

// ---------------------------------------------------------------------------
// Phase A: per (bh, chunk) U^T[dv, dk] = sum_i lam^(C-i) V[i,:]^T K[i,:]
// ---------------------------------------------------------------------------
__global__ __launch_bounds__(256) void chunk_kv()
{
    extern __shared__ unsigned pool[];
    unsigned* Vt = pool;          // [128 dv][68]
    unsigned* Kt = pool + 8704;   // [128 dk][68]

    const int tid  = threadIdx.x;
    const int lane = tid & 31;
    const int wid  = tid >> 5;
    const int gq = lane >> 2;
    const int tq = lane & 3;
    const int wm = (wid & 3) * 32;
    const int wn = (wid >> 2) * 64;

    const int dvt = blockIdx.x & 3;
    const int dkt = blockIdx.x >> 2;
    const int c   = blockIdx.y;
    const int bh  = blockIdx.z;
    const int b = bh >> 2, h = bh & 3;
    const float lam = head_lam(h);

    const int rowbase = b * T_SEQ + c * CHK;
    const float* Vb = g_v + (size_t)rowbase * VDIM + h * DV + dvt * 128;
    const float* Kb = g_k + (size_t)rowbase * KDIM + h * DK + dkt * 128;

    float acc[2][8][4];
#pragma unroll
    for (int mt = 0; mt < 2; mt++)
#pragma unroll
        for (int nt = 0; nt < 8; nt++)
#pragma unroll
            for (int e = 0; e < 4; e++) acc[mt][nt][e] = 0.0f;

    for (int sh = 0; sh < 2; sh++) {
#pragma unroll
        for (int it = 0; it < 8; it++) {
            int id = it * 256 + tid;
            int n4 = id & 31;
            int i  = id >> 5;
            float4 v = *(const float4*)(Vb + (size_t)(sh * 64 + i) * VDIM + n4 * 4);
            Vt[(n4 * 4 + 0) * 68 + i] = f2tf(v.x);
            Vt[(n4 * 4 + 1) * 68 + i] = f2tf(v.y);
            Vt[(n4 * 4 + 2) * 68 + i] = f2tf(v.z);
            Vt[(n4 * 4 + 3) * 68 + i] = f2tf(v.w);
            float w = expf(lam * (float)(CHK - (sh * 64 + i)));
            float4 kv = *(const float4*)(Kb + (size_t)(sh * 64 + i) * KDIM + n4 * 4);
            Kt[(n4 * 4 + 0) * 68 + i] = f2tf(kv.x * w);
            Kt[(n4 * 4 + 1) * 68 + i] = f2tf(kv.y * w);
            Kt[(n4 * 4 + 2) * 68 + i] = f2tf(kv.z * w);
            Kt[(n4 * 4 + 3) * 68 + i] = f2tf(kv.w * w);
        }
        __syncthreads();
#pragma unroll
        for (int kk = 0; kk < 64; kk += 8) {
            unsigned af[2][4];
#pragma unroll
            for (int mt = 0; mt < 2; mt++) {
                int r = wm + mt * 16 + gq;
                af[mt][0] = Vt[r * 68 + kk + tq];
                af[mt][1] = Vt[(r + 8) * 68 + kk + tq];
                af[mt][2] = Vt[r * 68 + kk + 4 + tq];
                af[mt][3] = Vt[(r + 8) * 68 + kk + 4 + tq];
            }
#pragma unroll
            for (int nt = 0; nt < 8; nt++) {
                int cc = wn + nt * 8 + gq;
                unsigned bf[2];
                bf[0] = Kt[cc * 68 + kk + tq];
                bf[1] = Kt[cc * 68 + kk + 4 + tq];
#pragma unroll
                for (int mt = 0; mt < 2; mt++)
                    mma_tf32(acc[mt][nt], af[mt], bf);
            }
        }
        __syncthreads();
    }

    float* St = g_state + (size_t)(bh * NCH + c) * STSZ;
#pragma unroll
    for (int mt = 0; mt < 2; mt++) {
        int r0 = dvt * 128 + wm + mt * 16 + gq;
#pragma unroll
        for (int nt = 0; nt < 8; nt++) {
            int cc = dkt * 128 + wn + nt * 8 + tq * 2;
            *(float2*)(St + (size_t)r0 * DK + cc)       = make_float2(acc[mt][nt][0], acc[mt][nt][1]);
            *(float2*)(St + (size_t)(r0 + 8) * DK + cc) = make_float2(acc[mt][nt][2], acc[mt][nt][3]);
        }
    }
}

// ---------------------------------------------------------------------------
// Phase B: prefix scan; stores tf32-rounded State snapshots (accum fp32).
// ---------------------------------------------------------------------------
__global__ __launch_bounds__(256) void state_scan()
{
    int tid4 = blockIdx.x * 256 + threadIdx.x;
    int bh   = tid4 >> 15;
    int off  = (tid4 & 32767) * 4;
    const float d = expf(head_lam(bh & 3) * (float)CHK);

    float* base = g_state + (size_t)bh * NCH * STSZ + off;
    float4 s = make_float4(0.f, 0.f, 0.f, 0.f);
#pragma unroll
    for (int c = 0; c < NCH; c++) {
        float4 u = *(float4*)(base + (size_t)c * STSZ);
        *(float4*)(base + (size_t)c * STSZ) =
            make_float4(roundtf(s.x), roundtf(s.y), roundtf(s.z), roundtf(s.w));
        s.x = d * s.x + u.x;
        s.y = d * s.y + u.y;
        s.z = d * s.z + u.z;
        s.w = d * s.w + u.w;
    }
}

// ---------------------------------------------------------------------------
// Phase C: O[128,128] = Qhat @ State^T + (mask . Q K^T) @ V
// ---------------------------------------------------------------------------
constexpr int QS_OFF = 0;
constexpr int BS_OFF = 4608;
constexpr int SS_OFF = 9216;
constexpr int VT_OFF = 17920;
constexpr int POOLC_WORDS = 26624;

__global__ __launch_bounds__(256) void chunk_out()
{
    extern __shared__ unsigned pool[];
    unsigned* Qs = pool + QS_OFF;
    unsigned* Bs = pool + BS_OFF;
    unsigned* Ss = pool + SS_OFF;
    unsigned* Vt = pool + VT_OFF;

    const int tid  = threadIdx.x;
    const int lane = tid & 31;
    const int wid  = tid >> 5;
    const int gq = lane >> 2;
    const int tq = lane & 3;
    const int wm  = (wid & 3) * 32;
    const int wn  = (wid >> 2) * 64;
    const int wns = (wid >> 2) * 32;

    const int dvt = blockIdx.x;
    const int c   = blockIdx.y;
    const int bh  = blockIdx.z;
    const int b = bh >> 2, h = bh & 3;
    const float lam = head_lam(h);

    const int rowbase = b * T_SEQ + c * CHK;
    const float* Qb = g_q + (size_t)rowbase * KDIM + h * DK;
    const float* Kb = g_k + (size_t)rowbase * KDIM + h * DK;
    const float* Vb = g_v + (size_t)rowbase * VDIM + h * DV + dvt * 128;
    const float* St = g_state + (size_t)(bh * NCH + c) * STSZ + (size_t)dvt * 128 * DK;

    float oacc[2][8][4];
#pragma unroll
    for (int mt = 0; mt < 2; mt++)
#pragma unroll
        for (int nt = 0; nt < 8; nt++)
#pragma unroll
            for (int e = 0; e < 4; e++) oacc[mt][nt][e] = 0.0f;

    // cross term
    for (int kc = 0; kc < DK; kc += 32) {
#pragma unroll
        for (int it = 0; it < 4; it++) {
            int id  = it * 256 + tid;
            int row = id >> 3;
            int kq  = (id & 7) * 4;
            float w = expf(lam * (float)row);
            float4 q = *(const float4*)(Qb + (size_t)row * KDIM + kc + kq);
            *(uint4*)&Qs[row * 36 + kq] =
                make_uint4(f2tf(q.x * w), f2tf(q.y * w), f2tf(q.z * w), f2tf(q.w * w));
            float4 s = *(const float4*)(St + (size_t)row * DK + kc + kq);
            *(uint4*)&Bs[row * 36 + kq] =
                make_uint4(f2tf(s.x), f2tf(s.y), f2tf(s.z), f2tf(s.w));
        }
        __syncthreads();
#pragma unroll
        for (int kk = 0; kk < 32; kk += 8) {
            unsigned af[2][4];
#pragma unroll
            for (int mt = 0; mt < 2; mt++) {
                int r = wm + mt * 16 + gq;
                af[mt][0] = Qs[r * 36 + kk + tq];
                af[mt][1] = Qs[(r + 8) * 36 + kk + tq];
                af[mt][2] = Qs[r * 36 + kk + 4 + tq];
                af[mt][3] = Qs[(r + 8) * 36 + kk + 4 + tq];
            }
#pragma unroll
            for (int nt = 0; nt < 8; nt++) {
                int cc = wn + nt * 8 + gq;
                unsigned bf[2];
                bf[0] = Bs[cc * 36 + kk + tq];
                bf[1] = Bs[cc * 36 + kk + 4 + tq];
#pragma unroll
                for (int mt = 0; mt < 2; mt++)
                    mma_tf32(oacc[mt][nt], af[mt], bf);
            }
        }
        __syncthreads();
    }

    // intra term
    for (int sh = 0; sh < 2; sh++) {
        float sacc[2][4][4];
#pragma unroll
        for (int mt = 0; mt < 2; mt++)
#pragma unroll
            for (int nt = 0; nt < 4; nt++)
#pragma unroll
                for (int e = 0; e < 4; e++) sacc[mt][nt][e] = 0.0f;

        for (int kc = 0; kc < DK; kc += 32) {
#pragma unroll
            for (int it = 0; it < 4; it++) {
                int id  = it * 256 + tid;
                int row = id >> 3;
                int kq  = (id & 7) * 4;
                float4 q = *(const float4*)(Qb + (size_t)row * KDIM + kc + kq);
                *(uint4*)&Qs[row * 36 + kq] =
                    make_uint4(f2tf(q.x), f2tf(q.y), f2tf(q.z), f2tf(q.w));
            }
#pragma unroll
            for (int it = 0; it < 2; it++) {
                int id  = it * 256 + tid;
                int row = id >> 3;
                int kq  = (id & 7) * 4;
                float4 kv = *(const float4*)(Kb + (size_t)(sh * 64 + row) * KDIM + kc + kq);
                *(uint4*)&Bs[row * 36 + kq] =
                    make_uint4(f2tf(kv.x), f2tf(kv.y), f2tf(kv.z), f2tf(kv.w));
            }
            __syncthreads();
#pragma unroll
            for (int kk = 0; kk < 32; kk += 8) {
                unsigned af[2][4];
#pragma unroll
                for (int mt = 0; mt < 2; mt++) {
                    int r = wm + mt * 16 + gq;
                    af[mt][0] = Qs[r * 36 + kk + tq];
                    af[mt][1] = Qs[(r + 8) * 36 + kk + tq];
                    af[mt][2] = Qs[r * 36 + kk + 4 + tq];
                    af[mt][3] = Qs[(r + 8) * 36 + kk + 4 + tq];
                }
#pragma unroll
                for (int nt = 0; nt < 4; nt++) {
                    int cc = wns + nt * 8 + gq;
                    unsigned bf[2];
                    bf[0] = Bs[cc * 36 + kk + tq];
                    bf[1] = Bs[cc * 36 + kk + 4 + tq];
#pragma unroll
                    for (int mt = 0; mt < 2; mt++)
                        mma_tf32(sacc[mt][nt], af[mt], bf);
                }
            }
            __syncthreads();
        }

#pragma unroll
        for (int mt = 0; mt < 2; mt++) {
#pragma unroll
            for (int nt = 0; nt < 4; nt++) {
#pragma unroll
                for (int e = 0; e < 4; e++) {
                    int r  = wm + mt * 16 + gq + (e >> 1) * 8;
                    int cl = wns + nt * 8 + tq * 2 + (e & 1);
                    int s  = sh * 64 + cl;
                    float w = (r >= s) ? expf(lam * (float)(r - s)) : 0.0f;
                    Ss[r * 68 + cl] = f2tf(sacc[mt][nt][e] * w);
                }
            }
        }
#pragma unroll
        for (int it = 0; it < 8; it++) {
            int id = it * 256 + tid;
            int n4 = id & 31;
            int i  = id >> 5;
            float4 v = *(const float4*)(Vb + (size_t)(sh * 64 + i) * VDIM + n4 * 4);
            Vt[(n4 * 4 + 0) * 68 + i] = f2tf(v.x);
            Vt[(n4 * 4 + 1) * 68 + i] = f2tf(v.y);
            Vt[(n4 * 4 + 2) * 68 + i] = f2tf(v.z);
            Vt[(n4 * 4 + 3) * 68 + i] = f2tf(v.w);
        }
        __syncthreads();

#pragma unroll
        for (int kk = 0; kk < 64; kk += 8) {
            unsigned af[2][4];
#pragma unroll
            for (int mt = 0; mt < 2; mt++) {
                int r = wm + mt * 16 + gq;
                af[mt][0] = Ss[r * 68 + kk + tq];
                af[mt][1] = Ss[(r + 8) * 68 + kk + tq];
                af[mt][2] = Ss[r * 68 + kk + 4 + tq];
                af[mt][3] = Ss[(r + 8) * 68 + kk + 4 + tq];
            }
#pragma unroll
            for (int nt = 0; nt < 8; nt++) {
                int cc = wn + nt * 8 + gq;
                unsigned bf[2];
                bf[0] = Vt[cc * 68 + kk + tq];
                bf[1] = Vt[cc * 68 + kk + 4 + tq];
#pragma unroll
                for (int mt = 0; mt < 2; mt++)
                    mma_tf32(oacc[mt][nt], af[mt], bf);
            }
        }
        __syncthreads();
    }

#pragma unroll
    for (int mt = 0; mt < 2; mt++) {
        int r0 = wm + mt * 16 + gq;
#pragma unroll
        for (int nt = 0; nt < 8; nt++) {
            int cc = h * DV + dvt * 128 + wn + nt * 8 + tq * 2;
            size_t row = (size_t)(rowbase + r0);
            *(float2*)(g_o + row * VDIM + cc) =
                make_float2(oacc[mt][nt][0], oacc[mt][nt][1]);
            *(float2*)(g_o + (row + 8) * VDIM + cc) =
                make_float2(oacc[mt][nt][2], oacc[mt][nt][3]);
        }
    }
}

// ---------------------------------------------------------------------------
// RMSNorm * g_norm_w * silu(g); writes tf32-rounded o (feeds out_gemm).
// ---------------------------------------------------------------------------
__global__ __launch_bounds__(256) void gate_kernel(const float* __restrict__ gw)
{
    __shared__ float ws[8];
    const int blk = blockIdx.x;
    const int tid = threadIdx.x;
    const size_t base = (size_t)(blk >> 2) * VDIM + (size_t)(blk & 3) * DV;

    float2 o2 = *(float2*)(g_o + base + tid * 2);
    float p = o2.x * o2.x + o2.y * o2.y;
#pragma unroll
    for (int off = 16; off > 0; off >>= 1) p += __shfl_xor_sync(0xffffffffu, p, off);
    if ((tid & 31) == 0) ws[tid >> 5] = p;
    __syncthreads();
    float tot = ws[0] + ws[1] + ws[2] + ws[3] + ws[4] + ws[5] + ws[6] + ws[7];
    float rms = rsqrtf(tot * (1.0f / (float)DV) + 1e-5f);

    const int c = tid * 2;
    float2 g2 = *(const float2*)(g_g + base + c);
    float s0 = g2.x / (1.0f + expf(-g2.x));
    float s1 = g2.y / (1.0f + expf(-g2.y));
    o2.x = roundtf(o2.x * rms * gw[c] * s0);
    o2.y = roundtf(o2.y * rms * gw[c + 1] * s1);
    *(float2*)(g_o + base + c) = o2;
}

// ---------------------------------------------------------------------------
extern "C" void kernel_launch(void* const* d_in, const int* in_sizes, int n_in,
                              void* d_out, int out_size)
{
    const float* x  = (const float*)d_in[0];
    const float* Wq = (const float*)d_in[1];
    const float* Wk = (const float*)d_in[2];
    const float* Wv = (const float*)d_in[3];
    const float* Wg = (const float*)d_in[4];
    const float* Wo = (const float*)d_in[5];
    const float* gw = (const float*)d_in[6];
    float* out = (float*)d_out;

    cudaFuncSetAttribute(proj_gemm, cudaFuncAttributeMaxDynamicSharedMemorySize, GEMM_SMEM);
    cudaFuncSetAttribute(out_gemm,  cudaFuncAttributeMaxDynamicSharedMemorySize, GEMM_SMEM);
    cudaFuncSetAttribute(chunk_kv,  cudaFuncAttributeMaxDynamicSharedMemorySize, 17408 * 4);
    cudaFuncSetAttribute(chunk_out, cudaFuncAttributeMaxDynamicSharedMemorySize, POOLC_WORDS * 4);

    // Pre-round inputs to tf32 (mma truncation then == identity; raw cp.async ok)
    round_copy<<<4096, 256>>>(x,  5, 0,       1048576);
    round_copy<<<1024, 256>>>(Wq, 6, WQ_OFF,  262144);
    round_copy<<<1024, 256>>>(Wk, 6, WK_OFF,  262144);
    round_copy<<<2048, 256>>>(Wv, 6, WV_OFF,  524288);
    round_copy<<<2048, 256>>>(Wg, 6, WG_OFF,  524288);
    round_copy<<<2048, 256>>>(Wo, 6, WO_OFF,  524288);

    // Fused projections (256-wide N tiles)
    dim3 gp(24, 32);
    proj_gemm<<<gp, 256, GEMM_SMEM>>>();

    rope_kernel<<<(NB * T_SEQ * NH * 128) / 256, 256>>>();

    dim3 ga(8, NCH, NB * NH);
    chunk_kv<<<ga, 256, 17408 * 4>>>();

    state_scan<<<1024, 256>>>();

    dim3 gc(4, NCH, NB * NH);
    chunk_out<<<gc, 256, POOLC_WORDS * 4>>>();

    gate_kernel<<<MROWS * NH, 256>>>(gw);

    dim3 go(4, 32);
    out_gemm<<<go, 256, GEMM_SMEM>>>(out);
}

// round 9
// speedup vs baseline: 1.1924x; 1.1924x over previous
#include <cuda_runtime.h>
#include <math.h>
#include <stdint.h>

// Problem constants
constexpr int T_SEQ  = 2048;
constexpr int NB     = 2;
constexpr int NH     = 4;
constexpr int DK     = 256;
constexpr int DV     = 512;
constexpr int DMODEL = 1024;
constexpr int KDIM   = NH * DK;    // 1024
constexpr int VDIM   = NH * DV;    // 2048
constexpr int MROWS  = NB * T_SEQ; // 4096
constexpr int CHK    = 128;
constexpr int NCH    = T_SEQ / CHK; // 16
constexpr int STSZ   = DV * DK;     // 131072

// Scratch (device globals; no allocations allowed)
__device__ __align__(128) float g_q[MROWS * KDIM];
__device__ __align__(128) float g_k[MROWS * KDIM];
__device__ __align__(128) float g_v[MROWS * VDIM];
__device__ __align__(128) float g_g[MROWS * VDIM];
__device__ __align__(128) float g_o[MROWS * VDIM];
__device__ __align__(128) float g_x[MROWS * DMODEL];         // rounded x
__device__ __align__(128) float g_w[8 * 1024 * 1024];        // rounded weights
__device__ __align__(128) float g_state[NB * NH * NCH * STSZ];

// weight offsets in g_w (floats)
constexpr long long WQ_OFF = 0;
constexpr long long WK_OFF = 1048576;
constexpr long long WV_OFF = 2097152;
constexpr long long WG_OFF = 4194304;
constexpr long long WO_OFF = 6291456;

__device__ __forceinline__ unsigned f2tf(float f) {
    unsigned u;
    asm("cvt.rna.tf32.f32 %0, %1;" : "=r"(u) : "f"(f));
    return u;
}
__device__ __forceinline__ float roundtf(float f) { return __uint_as_float(f2tf(f)); }

__device__ __forceinline__ void mma_tf32(float* c, const unsigned* a, const unsigned* b) {
    asm volatile(
        "mma.sync.aligned.m16n8k8.row.col.f32.tf32.tf32.f32 "
        "{%0,%1,%2,%3}, {%4,%5,%6,%7}, {%8,%9}, {%0,%1,%2,%3};\n"
        : "+f"(c[0]), "+f"(c[1]), "+f"(c[2]), "+f"(c[3])
        : "r"(a[0]), "r"(a[1]), "r"(a[2]), "r"(a[3]), "r"(b[0]), "r"(b[1]));
}

__device__ __forceinline__ void ldsm_x4(unsigned* r, uint32_t addr) {
    asm volatile("ldmatrix.sync.aligned.m8n8.x4.shared.b16 {%0,%1,%2,%3}, [%4];"
                 : "=r"(r[0]), "=r"(r[1]), "=r"(r[2]), "=r"(r[3]) : "r"(addr));
}

__device__ __forceinline__ float head_lam(int h) {
    return logf(1.0f - exp2f(-5.0f - (float)h));
}

__device__ __forceinline__ void cpasync16(unsigned dst, const void* src) {
    asm volatile("cp.async.cg.shared.global [%0], [%1], 16;\n" :: "r"(dst), "l"(src));
}
__device__ __forceinline__ void cp_commit() {
    asm volatile("cp.async.commit_group;\n" ::: "memory");
}
__device__ __forceinline__ void cp_wait1() {
    asm volatile("cp.async.wait_group 1;\n" ::: "memory");
}
__device__ __forceinline__ void cp_wait0() {
    asm volatile("cp.async.wait_group 0;\n" ::: "memory");
}
__device__ __forceinline__ uint32_t smem_u32(const void* p) {
    uint32_t a;
    asm("{ .reg .u64 t; cvta.to.shared.u64 t, %1; cvt.u32.u64 %0, t; }" : "=r"(a) : "l"(p));
    return a;
}

// ---------------------------------------------------------------------------
// Rounding copy: src (external fp32) -> tf32-rounded scratch (g_x or g_w+off)
// ---------------------------------------------------------------------------
__global__ __launch_bounds__(256) void round_copy(
    const float* __restrict__ src, int dsel, long long doff, int n4)
{
    float* dst = ((dsel == 5) ? g_x : g_w) + doff;
    int i = blockIdx.x * 256 + threadIdx.x;
    if (i < n4) {
        float4 v = ((const float4*)src)[i];
        ((float4*)dst)[i] = make_float4(roundtf(v.x), roundtf(v.y),
                                        roundtf(v.z), roundtf(v.w));
    }
}

// ---------------------------------------------------------------------------
// Pipelined TF32 GEMM with ldmatrix fragments.
// CTA tile 128x128, BK=32, 2-stage cp.async, 8 warps (4m x 2n), warp 32x64.
// Smem layout: row-major 128B rows, XOR-swizzled 16B granules (g ^= row&7).
// Inputs must already be tf32-rounded (raw bytes fed to mma).
// ---------------------------------------------------------------------------
constexpr int AT_B   = 128 * 128;           // 16 KB A tile
constexpr int STG_B  = 2 * AT_B;            // A+B per stage = 32 KB
constexpr int GEMM_SMEM = 2 * STG_B;        // 65536 bytes

__device__ __forceinline__ void gemm_pipe(
    const float* __restrict__ Ab, const float* __restrict__ Wb,
    float* __restrict__ Cb, int ldc, int K, int roundC, char* smem)
{
    const int tid  = threadIdx.x;
    const int lane = tid & 31;
    const int wid  = tid >> 5;
    const int wm = (wid & 3) * 32;
    const int wn = (wid >> 2) * 64;
    const int gq = lane >> 2;
    const int tq = lane & 3;
    const int nk = K >> 5;
    const uint32_t sa = smem_u32(smem);

    // ldmatrix per-lane row/granule selectors
    const int a_row  = (lane & 7) + ((lane >> 3) & 1) * 8;  // + wm + mt*16
    const int a_gsel = lane >> 4;
    const int b_row  = (lane & 7) + (lane >> 4) * 8;        // + wn + ntp*16
    const int b_gsel = (lane >> 3) & 1;

    float acc[2][8][4];
#pragma unroll
    for (int mt = 0; mt < 2; mt++)
#pragma unroll
        for (int nt = 0; nt < 8; nt++)
#pragma unroll
            for (int e = 0; e < 4; e++) acc[mt][nt][e] = 0.0f;

    auto cp_chunk = [&](int c) {
        uint32_t ab = sa + (c & 1) * STG_B;
        uint32_t bb = ab + AT_B;
        const float* Ap = Ab + c * 32;
        const float* Bp = Wb + c * 32;
#pragma unroll
        for (int i = 0; i < 4; i++) {
            int id = i * 256 + tid;
            int row = id >> 3, g = id & 7;
            cpasync16(ab + row * 128 + ((g ^ (row & 7)) << 4),
                      Ap + (size_t)row * K + g * 4);
        }
#pragma unroll
        for (int i = 0; i < 4; i++) {
            int id = i * 256 + tid;
            int row = id >> 3, g = id & 7;
            cpasync16(bb + row * 128 + ((g ^ (row & 7)) << 4),
                      Bp + (size_t)row * K + g * 4);
        }
        cp_commit();
    };

    cp_chunk(0);

    for (int j = 0; j < nk; j++) {
        if (j + 1 < nk) { cp_chunk(j + 1); cp_wait1(); }
        else            { cp_wait0(); }
        __syncthreads();

        uint32_t ab = sa + (j & 1) * STG_B;
        uint32_t bb = ab + AT_B;
#pragma unroll
        for (int k8 = 0; k8 < 4; k8++) {
            const int gA = k8 * 2 + a_gsel;
            const int gB = k8 * 2 + b_gsel;
            unsigned af[2][4];
#pragma unroll
            for (int mt = 0; mt < 2; mt++) {
                int r = wm + mt * 16 + a_row;
                ldsm_x4(af[mt], ab + r * 128 + ((gA ^ (r & 7)) << 4));
            }
            unsigned bfr[4][4];
#pragma unroll
            for (int ntp = 0; ntp < 4; ntp++) {
                int r = wn + ntp * 16 + b_row;
                ldsm_x4(bfr[ntp], bb + r * 128 + ((gB ^ (r & 7)) << 4));
            }
#pragma unroll
            for (int ntp = 0; ntp < 4; ntp++) {
#pragma unroll
                for (int half = 0; half < 2; half++) {
                    unsigned bf[2] = { bfr[ntp][half * 2], bfr[ntp][half * 2 + 1] };
#pragma unroll
                    for (int mt = 0; mt < 2; mt++)
                        mma_tf32(acc[mt][ntp * 2 + half], af[mt], bf);
                }
            }
        }
        __syncthreads();
    }

#pragma unroll
    for (int mt = 0; mt < 2; mt++) {
        int r0 = wm + mt * 16 + gq;
#pragma unroll
        for (int nt = 0; nt < 8; nt++) {
            int cc = wn + nt * 8 + tq * 2;
            float2 v0 = make_float2(acc[mt][nt][0], acc[mt][nt][1]);
            float2 v1 = make_float2(acc[mt][nt][2], acc[mt][nt][3]);
            if (roundC) {
                v0.x = roundtf(v0.x); v0.y = roundtf(v0.y);
                v1.x = roundtf(v1.x); v1.y = roundtf(v1.y);
            }
            *(float2*)(Cb + (size_t)r0 * ldc + cc)       = v0;
            *(float2*)(Cb + (size_t)(r0 + 8) * ldc + cc) = v1;
        }
    }
}

// Fused projections: x @ {Wq,Wk,Wv,Wg}^T. grid (48, 32), 128-wide N tiles.
__global__ __launch_bounds__(256, 2) void proj_gemm()
{
    extern __shared__ char smem[];
    const int bnx = blockIdx.x;
    const int bm  = blockIdx.y * 128;

    const float* Wb; float* Cc; int ldc, col, roundC = 0;
    if (bnx < 8)       { Wb = g_w + WQ_OFF; Cc = g_q; ldc = 1024; col = bnx * 128; }
    else if (bnx < 16) { Wb = g_w + WK_OFF; Cc = g_k; ldc = 1024; col = (bnx - 8) * 128; }
    else if (bnx < 32) { Wb = g_w + WV_OFF; Cc = g_v; ldc = 2048; col = (bnx - 16) * 128; roundC = 1; }
    else               { Wb = g_w + WG_OFF; Cc = g_g; ldc = 2048; col = (bnx - 32) * 128; }

    gemm_pipe(g_x + (size_t)bm * DMODEL, Wb + (size_t)col * DMODEL,
              Cc + (size_t)bm * ldc + col, ldc, DMODEL, roundC, smem);
}

// Output projection: (g_o rounded) @ Wo^T -> out. grid (8, 32).
__global__ __launch_bounds__(256, 2) void out_gemm(float* __restrict__ out)
{
    extern __shared__ char smem[];
    const int bn = blockIdx.x * 128;
    const int bm = blockIdx.y * 128;
    gemm_pipe(g_o + (size_t)bm * VDIM, g_w + WO_OFF + (size_t)bn * VDIM,
              out + (size_t)bm * DMODEL + bn, DMODEL, VDIM, 0, smem);
}

// ---------------------------------------------------------------------------
// RoPE (in place on g_q, g_k) + q scale by dk^-0.5 (fp32 path as reference).
// ---------------------------------------------------------------------------
__global__ __launch_bounds__(256) void rope_kernel()
{
    int idx = blockIdx.x * 256 + threadIdx.x;
    int i  = idx & 127;
    int h  = (idx >> 7) & 3;
    int bt = idx >> 9;
    int t  = bt & (T_SEQ - 1);
    size_t base = (size_t)bt * KDIM + h * DK;

    float e    = (float)(2 * i) * (1.0f / 256.0f);
    float invf = 1.0f / powf(10000.0f, e);
    float ang  = (float)t * invf;
    float sn, cs;
    sincosf(ang, &sn, &cs);

    float q1 = g_q[base + i], q2 = g_q[base + 128 + i];
    g_q[base + i]       = (q1 * cs - q2 * sn) * 0.0625f;
    g_q[base + 128 + i] = (q1 * sn + q2 * cs) * 0.0625f;
    float k1 = g_k[base + i], k2 = g_k[base + 128 + i];
    g_k[base + i]       = k1 * cs - k2 * sn;
    g_k[base + 128 + i] = k1 * sn + k2 * cs;
}

// ---------------------------------------------------------------------------
// Phase A: per (bh, chunk) U^T[dv, dk] = sum_i lam^(C-i) V[i,:]^T K[i,:]
// ---------------------------------------------------------------------------
__global__ __launch_bounds__(256) void chunk_kv()
{
    extern __shared__ unsigned pool[];
    unsigned* Vt = pool;          // [128 dv][68]
    unsigned* Kt = pool + 8704;   // [128 dk][68]

    const int tid  = threadIdx.x;
    const int lane = tid & 31;
    const int wid  = tid >> 5;
    const int gq = lane >> 2;
    const int tq = lane & 3;
    const int wm = (wid & 3) * 32;
    const int wn = (wid >> 2) * 64;

    const int dvt = blockIdx.x & 3;
    const int dkt = blockIdx.x >> 2;
    const int c   = blockIdx.y;
    const int bh  = blockIdx.z;
    const int b = bh >> 2, h = bh & 3;
    const float lam = head_lam(h);

    const int rowbase = b * T_SEQ + c * CHK;
    const float* Vb = g_v + (size_t)rowbase * VDIM + h * DV + dvt * 128;
    const float* Kb = g_k + (size_t)rowbase * KDIM + h * DK + dkt * 128;

    float acc[2][8][4];
#pragma unroll
    for (int mt = 0; mt < 2; mt++)
#pragma unroll
        for (int nt = 0; nt < 8; nt++)
#pragma unroll
            for (int e = 0; e < 4; e++) acc[mt][nt][e] = 0.0f;

    for (int sh = 0; sh < 2; sh++) {
#pragma unroll
        for (int it = 0; it < 8; it++) {
            int id = it * 256 + tid;
            int n4 = id & 31;
            int i  = id >> 5;
            float4 v = *(const float4*)(Vb + (size_t)(sh * 64 + i) * VDIM + n4 * 4);
            Vt[(n4 * 4 + 0) * 68 + i] = f2tf(v.x);
            Vt[(n4 * 4 + 1) * 68 + i] = f2tf(v.y);
            Vt[(n4 * 4 + 2) * 68 + i] = f2tf(v.z);
            Vt[(n4 * 4 + 3) * 68 + i] = f2tf(v.w);
            float w = expf(lam * (float)(CHK - (sh * 64 + i)));
            float4 kv = *(const float4*)(Kb + (size_t)(sh * 64 + i) * KDIM + n4 * 4);
            Kt[(n4 * 4 + 0) * 68 + i] = f2tf(kv.x * w);
            Kt[(n4 * 4 + 1) * 68 + i] = f2tf(kv.y * w);
            Kt[(n4 * 4 + 2) * 68 + i] = f2tf(kv.z * w);
            Kt[(n4 * 4 + 3) * 68 + i] = f2tf(kv.w * w);
        }
        __syncthreads();
#pragma unroll
        for (int kk = 0; kk < 64; kk += 8) {
            unsigned af[2][4];
#pragma unroll
            for (int mt = 0; mt < 2; mt++) {
                int r = wm + mt * 16 + gq;
                af[mt][0] = Vt[r * 68 + kk + tq];
                af[mt][1] = Vt[(r + 8) * 68 + kk + tq];
                af[mt][2] = Vt[r * 68 + kk + 4 + tq];
                af[mt][3] = Vt[(r + 8) * 68 + kk + 4 + tq];
            }
#pragma unroll
            for (int nt = 0; nt < 8; nt++) {
                int cc = wn + nt * 8 + gq;
                unsigned bf[2];
                bf[0] = Kt[cc * 68 + kk + tq];
                bf[1] = Kt[cc * 68 + kk + 4 + tq];
#pragma unroll
                for (int mt = 0; mt < 2; mt++)
                    mma_tf32(acc[mt][nt], af[mt], bf);
            }
        }
        __syncthreads();
    }

    float* St = g_state + (size_t)(bh * NCH + c) * STSZ;
#pragma unroll
    for (int mt = 0; mt < 2; mt++) {
        int r0 = dvt * 128 + wm + mt * 16 + gq;
#pragma unroll
        for (int nt = 0; nt < 8; nt++) {
            int cc = dkt * 128 + wn + nt * 8 + tq * 2;
            *(float2*)(St + (size_t)r0 * DK + cc)       = make_float2(acc[mt][nt][0], acc[mt][nt][1]);
            *(float2*)(St + (size_t)(r0 + 8) * DK + cc) = make_float2(acc[mt][nt][2], acc[mt][nt][3]);
        }
    }
}

// ---------------------------------------------------------------------------
// Phase B: prefix scan; stores tf32-rounded State snapshots (accum fp32).
// ---------------------------------------------------------------------------
__global__ __launch_bounds__(256) void state_scan()
{
    int tid4 = blockIdx.x * 256 + threadIdx.x;
    int bh   = tid4 >> 15;
    int off  = (tid4 & 32767) * 4;
    const float d = expf(head_lam(bh & 3) * (float)CHK);

    float* base = g_state + (size_t)bh * NCH * STSZ + off;
    float4 s = make_float4(0.f, 0.f, 0.f, 0.f);
#pragma unroll
    for (int c = 0; c < NCH; c++) {
        float4 u = *(float4*)(base + (size_t)c * STSZ);
        *(float4*)(base + (size_t)c * STSZ) =
            make_float4(roundtf(s.x), roundtf(s.y), roundtf(s.z), roundtf(s.w));
        s.x = d * s.x + u.x;
        s.y = d * s.y + u.y;
        s.z = d * s.z + u.z;
        s.w = d * s.w + u.w;
    }
}

// ---------------------------------------------------------------------------
// Phase C: O[128,128] = Qhat @ State^T + (mask . Q K^T) @ V
// ---------------------------------------------------------------------------
constexpr int QS_OFF = 0;
constexpr int BS_OFF = 4608;
constexpr int SS_OFF = 9216;
constexpr int VT_OFF = 17920;
constexpr int POOLC_WORDS = 26624;

__global__ __launch_bounds__(256) void chunk_out()
{
    extern __shared__ unsigned pool[];
    unsigned* Qs = pool + QS_OFF;
    unsigned* Bs = pool + BS_OFF;
    unsigned* Ss = pool + SS_OFF;
    unsigned* Vt = pool + VT_OFF;

    const int tid  = threadIdx.x;
    const int lane = tid & 31;
    const int wid  = tid >> 5;
    const int gq = lane >> 2;
    const int tq = lane & 3;
    const int wm  = (wid & 3) * 32;
    const int wn  = (wid >> 2) * 64;
    const int wns = (wid >> 2) * 32;

    const int dvt = blockIdx.x;
    const int c   = blockIdx.y;
    const int bh  = blockIdx.z;
    const int b = bh >> 2, h = bh & 3;
    const float lam = head_lam(h);

    const int rowbase = b * T_SEQ + c * CHK;
    const float* Qb = g_q + (size_t)rowbase * KDIM + h * DK;
    const float* Kb = g_k + (size_t)rowbase * KDIM + h * DK;
    const float* Vb = g_v + (size_t)rowbase * VDIM + h * DV + dvt * 128;
    const float* St = g_state + (size_t)(bh * NCH + c) * STSZ + (size_t)dvt * 128 * DK;

    float oacc[2][8][4];
#pragma unroll
    for (int mt = 0; mt < 2; mt++)
#pragma unroll
        for (int nt = 0; nt < 8; nt++)
#pragma unroll
            for (int e = 0; e < 4; e++) oacc[mt][nt][e] = 0.0f;

    // cross term
    for (int kc = 0; kc < DK; kc += 32) {
#pragma unroll
        for (int it = 0; it < 4; it++) {
            int id  = it * 256 + tid;
            int row = id >> 3;
            int kq  = (id & 7) * 4;
            float w = expf(lam * (float)row);
            float4 q = *(const float4*)(Qb + (size_t)row * KDIM + kc + kq);
            *(uint4*)&Qs[row * 36 + kq] =
                make_uint4(f2tf(q.x * w), f2tf(q.y * w), f2tf(q.z * w), f2tf(q.w * w));
            float4 s = *(const float4*)(St + (size_t)row * DK + kc + kq);
            *(uint4*)&Bs[row * 36 + kq] =
                make_uint4(f2tf(s.x), f2tf(s.y), f2tf(s.z), f2tf(s.w));
        }
        __syncthreads();
#pragma unroll
        for (int kk = 0; kk < 32; kk += 8) {
            unsigned af[2][4];
#pragma unroll
            for (int mt = 0; mt < 2; mt++) {
                int r = wm + mt * 16 + gq;
                af[mt][0] = Qs[r * 36 + kk + tq];
                af[mt][1] = Qs[(r + 8) * 36 + kk + tq];
                af[mt][2] = Qs[r * 36 + kk + 4 + tq];
                af[mt][3] = Qs[(r + 8) * 36 + kk + 4 + tq];
            }
#pragma unroll
            for (int nt = 0; nt < 8; nt++) {
                int cc = wn + nt * 8 + gq;
                unsigned bf[2];
                bf[0] = Bs[cc * 36 + kk + tq];
                bf[1] = Bs[cc * 36 + kk + 4 + tq];
#pragma unroll
                for (int mt = 0; mt < 2; mt++)
                    mma_tf32(oacc[mt][nt], af[mt], bf);
            }
        }
        __syncthreads();
    }

    // intra term
    for (int sh = 0; sh < 2; sh++) {
        float sacc[2][4][4];
#pragma unroll
        for (int mt = 0; mt < 2; mt++)
#pragma unroll
            for (int nt = 0; nt < 4; nt++)
#pragma unroll
                for (int e = 0; e < 4; e++) sacc[mt][nt][e] = 0.0f;

        for (int kc = 0; kc < DK; kc += 32) {
#pragma unroll
            for (int it = 0; it < 4; it++) {
                int id  = it * 256 + tid;
                int row = id >> 3;
                int kq  = (id & 7) * 4;
                float4 q = *(const float4*)(Qb + (size_t)row * KDIM + kc + kq);
                *(uint4*)&Qs[row * 36 + kq] =
                    make_uint4(f2tf(q.x), f2tf(q.y), f2tf(q.z), f2tf(q.w));
            }
#pragma unroll
            for (int it = 0; it < 2; it++) {
                int id  = it * 256 + tid;
                int row = id >> 3;
                int kq  = (id & 7) * 4;
                float4 kv = *(const float4*)(Kb + (size_t)(sh * 64 + row) * KDIM + kc + kq);
                *(uint4*)&Bs[row * 36 + kq] =
                    make_uint4(f2tf(kv.x), f2tf(kv.y), f2tf(kv.z), f2tf(kv.w));
            }
            __syncthreads();
#pragma unroll
            for (int kk = 0; kk < 32; kk += 8) {
                unsigned af[2][4];
#pragma unroll
                for (int mt = 0; mt < 2; mt++) {
                    int r = wm + mt * 16 + gq;
                    af[mt][0] = Qs[r * 36 + kk + tq];
                    af[mt][1] = Qs[(r + 8) * 36 + kk + tq];
                    af[mt][2] = Qs[r * 36 + kk + 4 + tq];
                    af[mt][3] = Qs[(r + 8) * 36 + kk + 4 + tq];
                }
#pragma unroll
                for (int nt = 0; nt < 4; nt++) {
                    int cc = wns + nt * 8 + gq;
                    unsigned bf[2];
                    bf[0] = Bs[cc * 36 + kk + tq];
                    bf[1] = Bs[cc * 36 + kk + 4 + tq];
#pragma unroll
                    for (int mt = 0; mt < 2; mt++)
                        mma_tf32(sacc[mt][nt], af[mt], bf);
                }
            }
            __syncthreads();
        }

#pragma unroll
        for (int mt = 0; mt < 2; mt++) {
#pragma unroll
            for (int nt = 0; nt < 4; nt++) {
#pragma unroll
                for (int e = 0; e < 4; e++) {
                    int r  = wm + mt * 16 + gq + (e >> 1) * 8;
                    int cl = wns + nt * 8 + tq * 2 + (e & 1);
                    int s  = sh * 64 + cl;
                    float w = (r >= s) ? expf(lam * (float)(r - s)) : 0.0f;
                    Ss[r * 68 + cl] = f2tf(sacc[mt][nt][e] * w);
                }
            }
        }
#pragma unroll
        for (int it = 0; it < 8; it++) {
            int id = it * 256 + tid;
            int n4 = id & 31;
            int i  = id >> 5;
            float4 v = *(const float4*)(Vb + (size_t)(sh * 64 + i) * VDIM + n4 * 4);
            Vt[(n4 * 4 + 0) * 68 + i] = f2tf(v.x);
            Vt[(n4 * 4 + 1) * 68 + i] = f2tf(v.y);
            Vt[(n4 * 4 + 2) * 68 + i] = f2tf(v.z);
            Vt[(n4 * 4 + 3) * 68 + i] = f2tf(v.w);
        }
        __syncthreads();

#pragma unroll
        for (int kk = 0; kk < 64; kk += 8) {
            unsigned af[2][4];
#pragma unroll
            for (int mt = 0; mt < 2; mt++) {
                int r = wm + mt * 16 + gq;
                af[mt][0] = Ss[r * 68 + kk + tq];
                af[mt][1] = Ss[(r + 8) * 68 + kk + tq];
                af[mt][2] = Ss[r * 68 + kk + 4 + tq];
                af[mt][3] = Ss[(r + 8) * 68 + kk + 4 + tq];
            }
#pragma unroll
            for (int nt = 0; nt < 8; nt++) {
                int cc = wn + nt * 8 + gq;
                unsigned bf[2];
                bf[0] = Vt[cc * 68 + kk + tq];
                bf[1] = Vt[cc * 68 + kk + 4 + tq];
#pragma unroll
                for (int mt = 0; mt < 2; mt++)
                    mma_tf32(oacc[mt][nt], af[mt], bf);
            }
        }
        __syncthreads();
    }

#pragma unroll
    for (int mt = 0; mt < 2; mt++) {
        int r0 = wm + mt * 16 + gq;
#pragma unroll
        for (int nt = 0; nt < 8; nt++) {
            int cc = h * DV + dvt * 128 + wn + nt * 8 + tq * 2;
            size_t row = (size_t)(rowbase + r0);
            *(float2*)(g_o + row * VDIM + cc) =
                make_float2(oacc[mt][nt][0], oacc[mt][nt][1]);
            *(float2*)(g_o + (row + 8) * VDIM + cc) =
                make_float2(oacc[mt][nt][2], oacc[mt][nt][3]);
        }
    }
}

// ---------------------------------------------------------------------------
// RMSNorm * g_norm_w * silu(g); writes tf32-rounded o (feeds out_gemm).
// ---------------------------------------------------------------------------
__global__ __launch_bounds__(256) void gate_kernel(const float* __restrict__ gw)
{
    __shared__ float ws[8];
    const int blk = blockIdx.x;
    const int tid = threadIdx.x;
    const size_t base = (size_t)(blk >> 2) * VDIM + (size_t)(blk & 3) * DV;

    float2 o2 = *(float2*)(g_o + base + tid * 2);
    float p = o2.x * o2.x + o2.y * o2.y;
#pragma unroll
    for (int off = 16; off > 0; off >>= 1) p += __shfl_xor_sync(0xffffffffu, p, off);
    if ((tid & 31) == 0) ws[tid >> 5] = p;
    __syncthreads();
    float tot = ws[0] + ws[1] + ws[2] + ws[3] + ws[4] + ws[5] + ws[6] + ws[7];
    float rms = rsqrtf(tot * (1.0f / (float)DV) + 1e-5f);

    const int c = tid * 2;
    float2 g2 = *(const float2*)(g_g + base + c);
    float s0 = g2.x / (1.0f + expf(-g2.x));
    float s1 = g2.y / (1.0f + expf(-g2.y));
    o2.x = roundtf(o2.x * rms * gw[c] * s0);
    o2.y = roundtf(o2.y * rms * gw[c + 1] * s1);
    *(float2*)(g_o + base + c) = o2;
}

// ---------------------------------------------------------------------------
extern "C" void kernel_launch(void* const* d_in, const int* in_sizes, int n_in,
                              void* d_out, int out_size)
{
    const float* x  = (const float*)d_in[0];
    const float* Wq = (const float*)d_in[1];
    const float* Wk = (const float*)d_in[2];
    const float* Wv = (const float*)d_in[3];
    const float* Wg = (const float*)d_in[4];
    const float* Wo = (const float*)d_in[5];
    const float* gw = (const float*)d_in[6];
    float* out = (float*)d_out;

    cudaFuncSetAttribute(proj_gemm, cudaFuncAttributeMaxDynamicSharedMemorySize, GEMM_SMEM);
    cudaFuncSetAttribute(out_gemm,  cudaFuncAttributeMaxDynamicSharedMemorySize, GEMM_SMEM);
    cudaFuncSetAttribute(chunk_kv,  cudaFuncAttributeMaxDynamicSharedMemorySize, 17408 * 4);
    cudaFuncSetAttribute(chunk_out, cudaFuncAttributeMaxDynamicSharedMemorySize, POOLC_WORDS * 4);

    // Pre-round inputs to tf32 (mma truncation then == identity; raw cp.async ok)
    round_copy<<<4096, 256>>>(x,  5, 0,       1048576);
    round_copy<<<1024, 256>>>(Wq, 6, WQ_OFF,  262144);
    round_copy<<<1024, 256>>>(Wk, 6, WK_OFF,  262144);
    round_copy<<<2048, 256>>>(Wv, 6, WV_OFF,  524288);
    round_copy<<<2048, 256>>>(Wg, 6, WG_OFF,  524288);
    round_copy<<<2048, 256>>>(Wo, 6, WO_OFF,  524288);

    // Fused projections
    dim3 gp(48, 32);
    proj_gemm<<<gp, 256, GEMM_SMEM>>>();

    rope_kernel<<<(NB * T_SEQ * NH * 128) / 256, 256>>>();

    dim3 ga(8, NCH, NB * NH);
    chunk_kv<<<ga, 256, 17408 * 4>>>();

    state_scan<<<1024, 256>>>();

    dim3 gc(4, NCH, NB * NH);
    chunk_out<<<gc, 256, POOLC_WORDS * 4>>>();

    gate_kernel<<<MROWS * NH, 256>>>(gw);

    dim3 go(8, 32);
    out_gemm<<<go, 256, GEMM_SMEM>>>(out);
}